// round 2
// baseline (speedup 1.0000x reference)
#include <cuda_runtime.h>
#include <math.h>

#define Bn 4
#define Hn 512
#define Wn 512
#define Sn 40
#define PADc 32
#define OUTW 448
#define PI_F 3.14159265358979323846f

// ---------------- device scratch (statically allocated, no cudaMalloc) ----------------
__device__ float2 g_inc[Bn * Hn * Wn];
__device__ float2 g_b1[Bn * Hn * Wn];
__device__ float2 g_b2[Bn * Hn * Wn];
__device__ float2 g_prop[Hn * Wn];
__device__ float2 g_green[Hn * Wn];
__device__ float2 g_final[Hn * Wn];
__device__ float2 g_sampT[(size_t)Sn * Bn * Hn * Wn];   // [S][B][H][W] interleaved complex

__device__ __forceinline__ float2 cmul(float2 a, float2 b) {
    return make_float2(fmaf(a.x, b.x, -a.y * b.y), fmaf(a.x, b.y, a.y * b.x));
}

// ---------------- precompute prop / green / final multiplier ----------------
__global__ void k_precompute(const float* __restrict__ kz, const float* __restrict__ oabs,
                             const float* __restrict__ gmask, const float* __restrict__ oph) {
    int idx = blockIdx.x * blockDim.x + threadIdx.x;
    if (idx >= Hn * Wn) return;
    float k = kz[idx];
    float th = k * 0.1f;                 // kz * DZ
    float s, c;
    sincosf(th, &s, &c);
    float2 prop = make_float2(c, s);     // exp(i*kz*dz)
    g_prop[idx] = prop;
    // green = i*prop/(2kz) * mask ; kz >= 0.5 so finite
    float inv2k = 0.5f / k;
    float m = gmask[idx];
    g_green[idx] = make_float2(-s * inv2k * m, c * inv2k * m);
    // conj(prop^25)*prop^20 * otf_abs*exp(i*otf_phase) = otf_abs * exp(i*(otf_phase - 5*th))
    float ph = oph[idx] - 5.0f * th;
    float s2, c2;
    sincosf(ph, &s2, &c2);
    float a = oabs[idx];
    g_final[idx] = make_float2(a * c2, a * s2);
}

// ---------------- sample transpose [B,H,W,S] (re,im) -> [S,B,H,W] float2 ----------------
__global__ void k_transpose(const float* __restrict__ re, const float* __restrict__ im) {
    __shared__ float2 tile[128 * Sn];    // 40 KB
    const int wt = blockIdx.x;           // 0..3 (w tile of 128)
    const int bh = blockIdx.y;           // 0..B*H-1
    const int b = bh / Hn, h = bh % Hn;
    const size_t base = ((size_t)bh * Wn + (size_t)wt * 128) * Sn;
    for (int t = threadIdx.x; t < 128 * Sn; t += 256) {
        tile[t] = make_float2(re[base + t], im[base + t]);   // t = w'*40 + s, coalesced read
    }
    __syncthreads();
    for (int t = threadIdx.x; t < 128 * Sn; t += 256) {
        int s = t >> 7;          // t / 128
        int wp = t & 127;
        g_sampT[(((size_t)s * Bn + b) * Hn + h) * Wn + (size_t)wt * 128 + wp] = tile[wp * Sn + s];
    }
}

// ---------------- row FFT (512-pt radix-2 DIT, 256 threads / line) ----------------
#define PADIDX(i) ((i) + ((i) >> 4))

enum { M_PLAIN = 0, M_INIT = 1, M_SLAB = 2 };

template <int SIGN, int MODE>
__global__ void k_fft_row(const float2* __restrict__ in, float2* __restrict__ out,
                          const float* __restrict__ pre, const float* __restrict__ pim,
                          int slice) {
    __shared__ float2 sd[544];
    __shared__ float2 tw[256];
    const int t = threadIdx.x;                 // 0..255
    const int line = blockIdx.x;               // 0..B*H-1
    const size_t rb = (size_t)line * Wn;
    {
        float sv, cv;
        sincosf(PI_F * (float)t * (1.0f / 256.0f), &sv, &cv);
        tw[t] = make_float2(cv, sv);
    }
#pragma unroll
    for (int e = 0; e < 2; e++) {
        int i = t + 256 * e;
        int r = __brev(i) >> 23;               // 9-bit reversal
        float2 v;
        if (MODE == M_INIT)
            v = make_float2(pre[rb + i], pim[rb + i]);
        else
            v = in[rb + i];
        sd[PADIDX(r)] = v;
    }
    __syncthreads();
#pragma unroll
    for (int st = 0; st < 9; st++) {
        int half = 1 << st;
        int j = t & (half - 1);
        int i0 = ((t >> st) << (st + 1)) | j;
        float2 wv = tw[j << (8 - st)];
        float2 w = make_float2(wv.x, (SIGN > 0) ? wv.y : -wv.y);
        int p0 = PADIDX(i0), p1 = PADIDX(i0 + half);
        float2 a = sd[p0];
        float2 d = cmul(w, sd[p1]);
        sd[p0] = make_float2(a.x + d.x, a.y + d.y);
        sd[p1] = make_float2(a.x - d.x, a.y - d.y);
        __syncthreads();
    }
#pragma unroll
    for (int e = 0; e < 2; e++) {
        int i = t + 256 * e;
        float2 v = sd[PADIDX(i)];
        if (MODE == M_SLAB) {
            float2 sl = g_sampT[(size_t)slice * (Bn * Hn * Wn) + rb + i];
            v = cmul(v, sl);
            const float sc = 0.1f / (512.0f * 512.0f);   // DZ * 1/N^2 (ifft2 norm)
            v.x *= sc;
            v.y *= sc;
        }
        out[rb + i] = v;
    }
}

// ---------------- final row FFT: inverse + abs + crop to output ----------------
__global__ void k_row_final(const float2* __restrict__ in, float* __restrict__ out) {
    __shared__ float2 sd[544];
    __shared__ float2 tw[256];
    const int t = threadIdx.x;
    const int line = blockIdx.x;               // 0..B*448-1
    const int b = line / OUTW;
    const int ho = line - b * OUTW;            // output row
    const size_t rb = ((size_t)b * Hn + (ho + PADc)) * Wn;
    {
        float sv, cv;
        sincosf(PI_F * (float)t * (1.0f / 256.0f), &sv, &cv);
        tw[t] = make_float2(cv, sv);
    }
#pragma unroll
    for (int e = 0; e < 2; e++) {
        int i = t + 256 * e;
        int r = __brev(i) >> 23;
        sd[PADIDX(r)] = in[rb + i];
    }
    __syncthreads();
#pragma unroll
    for (int st = 0; st < 9; st++) {
        int half = 1 << st;
        int j = t & (half - 1);
        int i0 = ((t >> st) << (st + 1)) | j;
        float2 wv = tw[j << (8 - st)];
        float2 w = make_float2(wv.x, wv.y);    // SIGN = +1 (inverse)
        int p0 = PADIDX(i0), p1 = PADIDX(i0 + half);
        float2 a = sd[p0];
        float2 d = cmul(w, sd[p1]);
        sd[p0] = make_float2(a.x + d.x, a.y + d.y);
        sd[p1] = make_float2(a.x - d.x, a.y - d.y);
        __syncthreads();
    }
    const float sc = 1.0f / (512.0f * 512.0f);
#pragma unroll
    for (int e = 0; e < 2; e++) {
        int i = t + 256 * e;
        if (i >= PADc && i < Wn - PADc) {
            float2 v = sd[PADIDX(i)];
            out[((size_t)b * OUTW + ho) * OUTW + (i - PADc)] =
                sqrtf(v.x * v.x + v.y * v.y) * sc;
        }
    }
}

// ---------------- column FFT (8 columns / block, 512 threads) ----------------
enum { C_PLAIN = 0, C_COMBINE = 1, C_FINALIN = 2 };

template <int SIGN, int MODE>
__global__ void k_fft_col(const float2* __restrict__ in, float2* __restrict__ out) {
    __shared__ float2 sd[512 * 9];             // pitch 9 to break conflicts
    __shared__ float2 tw[256];
    const int c = threadIdx.x;                 // 0..7
    const int ty = threadIdx.y;                // 0..63
    const int tid = ty * 8 + c;
    const int col = blockIdx.x * 8 + c;
    const int b = blockIdx.y;
    const size_t base = (size_t)b * Hn * Wn;
    if (tid < 256) {
        float sv, cv;
        sincosf(PI_F * (float)tid * (1.0f / 256.0f), &sv, &cv);
        tw[tid] = make_float2(cv, sv);
    }
#pragma unroll
    for (int k = 0; k < 8; k++) {
        int r = ty + 64 * k;
        float2 v = in[base + (size_t)r * Wn + col];
        if (MODE == C_FINALIN) v = cmul(v, g_final[r * Wn + col]);
        int rr = __brev(r) >> 23;
        sd[rr * 9 + c] = v;
    }
    __syncthreads();
#pragma unroll
    for (int st = 0; st < 9; st++) {
        int half = 1 << st;
#pragma unroll
        for (int k = 0; k < 4; k++) {
            int bi = ty + 64 * k;              // butterfly index 0..255
            int j = bi & (half - 1);
            int i0 = ((bi >> st) << (st + 1)) | j;
            float2 wv = tw[j << (8 - st)];
            float2 w = make_float2(wv.x, (SIGN > 0) ? wv.y : -wv.y);
            float2 a = sd[i0 * 9 + c];
            float2 d = cmul(w, sd[(i0 + half) * 9 + c]);
            sd[i0 * 9 + c] = make_float2(a.x + d.x, a.y + d.y);
            sd[(i0 + half) * 9 + c] = make_float2(a.x - d.x, a.y - d.y);
        }
        __syncthreads();
    }
#pragma unroll
    for (int k = 0; k < 8; k++) {
        int r = ty + 64 * k;
        float2 v = sd[r * 9 + c];
        size_t gi = base + (size_t)r * Wn + col;
        if (MODE == C_COMBINE) {
            int hw = r * Wn + col;
            float2 u = cmul(g_inc[gi], g_prop[hw]);
            float2 s2 = cmul(g_green[hw], v);
            g_inc[gi] = make_float2(u.x + s2.x, u.y + s2.y);
        } else {
            out[gi] = v;
        }
    }
}

// ---------------- launch ----------------
extern "C" void kernel_launch(void* const* d_in, const int* in_sizes, int n_in,
                              void* d_out, int out_size) {
    (void)in_sizes; (void)n_in; (void)out_size;
    const float* sre  = (const float*)d_in[0];
    const float* sim  = (const float*)d_in[1];
    const float* pre  = (const float*)d_in[2];
    const float* pim  = (const float*)d_in[3];
    const float* kz   = (const float*)d_in[4];
    const float* oabs = (const float*)d_in[5];
    const float* gm   = (const float*)d_in[6];
    const float* oph  = (const float*)d_in[7];
    float* out = (float*)d_out;

    float2 *inc, *b1, *b2;
    cudaGetSymbolAddress((void**)&inc, g_inc);
    cudaGetSymbolAddress((void**)&b1, g_b1);
    cudaGetSymbolAddress((void**)&b2, g_b2);

    k_precompute<<<Hn, Wn>>>(kz, oabs, gm, oph);
    k_transpose<<<dim3(Wn / 128, Bn * Hn), 256>>>(sre, sim);

    dim3 cg(Wn / 8, Bn), cb(8, 64);

    // inc = fft2(planewave)
    k_fft_row<-1, M_INIT><<<Bn * Hn, 256>>>(nullptr, b1, pre, pim, 0);
    k_fft_col<-1, C_PLAIN><<<cg, cb>>>(b1, inc);

    for (int s = 0; s < Sn; s++) {
        // spatial = ifft2(inc) (unnormalized; norm folded into slab multiply)
        k_fft_col<+1, C_PLAIN><<<cg, cb>>>(inc, b1);
        // row inverse pass, then * slab * dz * 1/N^2
        k_fft_row<+1, M_SLAB><<<Bn * Hn, 256>>>(b1, b2, nullptr, nullptr, s);
        // forward fft2
        k_fft_row<-1, M_PLAIN><<<Bn * Hn, 256>>>(b2, b1, nullptr, nullptr, 0);
        // inc = inc*prop + green*result
        k_fft_col<-1, C_COMBINE><<<cg, cb>>>(b1, nullptr);
    }

    // final: inc *= exp(-5i*kz*dz)*otf  -> ifft2 -> abs -> crop
    k_fft_col<+1, C_FINALIN><<<cg, cb>>>(inc, b1);
    k_row_final<<<Bn * OUTW, 256>>>(b1, out);
}

// round 3
// speedup vs baseline: 2.3478x; 2.3478x over previous
#include <cuda_runtime.h>
#include <math.h>

#define Bn 4
#define Hn 512
#define Wn 512
#define Sn 40
#define PADc 32
#define OUTW 448

// ---------------- device scratch ----------------
__device__ float2 g_inc[Bn * Hn * Wn];
__device__ float2 g_b1[Bn * Hn * Wn];
__device__ float2 g_prop[Hn * Wn];
__device__ float2 g_green[Hn * Wn];
__device__ float2 g_final[Hn * Wn];
__device__ float2 g_tw[512];                          // exp(-2*pi*i*m/512)
__device__ float2 g_sampT[(size_t)Sn * Bn * Hn * Wn]; // [S][B][H][W]

__device__ __forceinline__ float2 cadd(float2 a, float2 b) { return make_float2(a.x + b.x, a.y + b.y); }
__device__ __forceinline__ float2 csub(float2 a, float2 b) { return make_float2(a.x - b.x, a.y - b.y); }
__device__ __forceinline__ float2 cmul(float2 a, float2 b) {
    return make_float2(fmaf(a.x, b.x, -a.y * b.y), fmaf(a.x, b.y, a.y * b.x));
}

// ---------------- 8-point DFT in registers (natural order in/out) ----------------
// SIGN=-1: forward (e^{-i}), SIGN=+1: inverse (unnormalized)
template <int SIGN>
__device__ __forceinline__ void fft8(float2* v) {
    const float s = (float)SIGN;
    const float r = 0.7071067811865476f;
    float2 t0 = cadd(v[0], v[4]), t1 = cadd(v[1], v[5]), t2 = cadd(v[2], v[6]), t3 = cadd(v[3], v[7]);
    float2 t4 = csub(v[0], v[4]), t5 = csub(v[1], v[5]), t6 = csub(v[2], v[6]), t7 = csub(v[3], v[7]);
    // t5 *= W8^1=(r, s r); t6 *= (0, s); t7 *= (-r, s r)
    t5 = make_float2(r * t5.x - s * r * t5.y, s * r * t5.x + r * t5.y);
    t6 = make_float2(-s * t6.y, s * t6.x);
    t7 = make_float2(-r * t7.x - s * r * t7.y, s * r * t7.x - r * t7.y);
    float2 p0 = cadd(t0, t2), p2 = csub(t0, t2), p1 = cadd(t1, t3), p3 = csub(t1, t3);
    p3 = make_float2(-s * p3.y, s * p3.x);
    float2 q0 = cadd(t4, t6), q2 = csub(t4, t6), q1 = cadd(t5, t7), q3 = csub(t5, t7);
    q3 = make_float2(-s * q3.y, s * q3.x);
    v[0] = cadd(p0, p1); v[4] = csub(p0, p1); v[2] = cadd(p2, p3); v[6] = csub(p2, p3);
    v[1] = cadd(q0, q1); v[5] = csub(q0, q1); v[3] = cadd(q2, q3); v[7] = csub(q2, q3);
}

// ---------------- 512-point FFT: 64 threads, 8 regs/thread, 2 smem exchanges ----------------
// entry: v[n1] = x[n1*64 + t]; exit: v[j2] = X[t + 64*j2]
// ex: per-FFT region, inner layout idx*9 (576 float2). Caller syncs before reuse.
template <int SIGN>
__device__ __forceinline__ void fft512(float2* v, float2* ex, const float2* tw, int t) {
    fft8<SIGN>(v);
#pragma unroll
    for (int k = 1; k < 8; k++) {
        float2 w = tw[t * k];
        if (SIGN > 0) w.y = -w.y;
        v[k] = cmul(v[k], w);
    }
#pragma unroll
    for (int k = 0; k < 8; k++) ex[t * 9 + k] = v[k];
    __syncthreads();
    const int m2 = t & 7, k1 = t >> 3;
#pragma unroll
    for (int m1 = 0; m1 < 8; m1++) v[m1] = ex[(m1 * 8 + m2) * 9 + k1];
    fft8<SIGN>(v);
#pragma unroll
    for (int j = 1; j < 8; j++) {
        float2 w = tw[8 * m2 * j];
        if (SIGN > 0) w.y = -w.y;
        v[j] = cmul(v[j], w);
    }
    __syncthreads();                    // all stage-2 reads done before overwrite
#pragma unroll
    for (int j = 0; j < 8; j++) ex[(j * 8 + m2) * 9 + k1] = v[j];
    __syncthreads();
    const int k1b = t & 7, j1 = t >> 3;
#pragma unroll
    for (int m = 0; m < 8; m++) v[m] = ex[(j1 * 8 + m) * 9 + k1b];
    fft8<SIGN>(v);                      // v[j2] = X[k1b + 8*j1 + 64*j2] = X[t + 64*j2]
}

// ---------------- precompute ----------------
__global__ void k_precompute(const float* __restrict__ kz, const float* __restrict__ oabs,
                             const float* __restrict__ gmask, const float* __restrict__ oph) {
    int idx = blockIdx.x * blockDim.x + threadIdx.x;
    if (blockIdx.x == 0) {
        float th = 6.283185307179586f * (float)threadIdx.x * (1.0f / 512.0f);
        float s, c;
        sincosf(th, &s, &c);
        g_tw[threadIdx.x] = make_float2(c, -s);  // e^{-2pi i m/512}
    }
    if (idx >= Hn * Wn) return;
    float k = kz[idx];
    float th = k * 0.1f;
    float s, c;
    sincosf(th, &s, &c);
    g_prop[idx] = make_float2(c, s);
    float inv2k = 0.5f / k;
    float m = gmask[idx];
    g_green[idx] = make_float2(-s * inv2k * m, c * inv2k * m);
    float ph = oph[idx] - 5.0f * th;    // conj(prop^25)*prop^20 folded into otf
    float s2, c2;
    sincosf(ph, &s2, &c2);
    float a = oabs[idx];
    g_final[idx] = make_float2(a * c2, a * s2);
}

// ---------------- sample transpose [B,H,W,S] -> [S,B,H,W] float2 ----------------
__global__ void k_transpose(const float* __restrict__ re, const float* __restrict__ im) {
    __shared__ float2 tile[128 * Sn];
    const int wt = blockIdx.x;
    const int bh = blockIdx.y;
    const int b = bh / Hn, h = bh % Hn;
    const size_t base = ((size_t)bh * Wn + (size_t)wt * 128) * Sn;
    for (int t = threadIdx.x; t < 128 * Sn; t += 256)
        tile[t] = make_float2(re[base + t], im[base + t]);
    __syncthreads();
    for (int t = threadIdx.x; t < 128 * Sn; t += 256) {
        int s = t >> 7;
        int wp = t & 127;
        g_sampT[(((size_t)s * Bn + b) * Hn + h) * Wn + (size_t)wt * 128 + wp] = tile[wp * Sn + s];
    }
}

// ---------------- row kernels: 4 lines/block, 64 threads/line ----------------
__global__ void k_row_init(const float* __restrict__ pre, const float* __restrict__ pim) {
    __shared__ float2 tw[512];
    __shared__ float2 ex[4 * 576];
    const int t = threadIdx.x, ly = threadIdx.y;
    const int line = blockIdx.x * 4 + ly;
    const size_t rb = (size_t)line * Wn;
    for (int i = ly * 64 + t; i < 512; i += 256) tw[i] = g_tw[i];
    float2 v[8];
#pragma unroll
    for (int n1 = 0; n1 < 8; n1++) {
        int i = n1 * 64 + t;
        v[n1] = make_float2(pre[rb + i], pim[rb + i]);
    }
    __syncthreads();
    fft512<-1>(v, ex + ly * 576, tw, t);
#pragma unroll
    for (int j = 0; j < 8; j++) g_b1[rb + t + 64 * j] = v[j];
}

// ifft-row -> *slab*dz/N^2 -> fft-row, all in one kernel
__global__ void k_row_fused(int slice) {
    __shared__ float2 tw[512];
    __shared__ float2 ex[4 * 576];
    const int t = threadIdx.x, ly = threadIdx.y;
    const int line = blockIdx.x * 4 + ly;
    const size_t rb = (size_t)line * Wn;
    for (int i = ly * 64 + t; i < 512; i += 256) tw[i] = g_tw[i];
    float2 v[8];
#pragma unroll
    for (int n1 = 0; n1 < 8; n1++) v[n1] = g_b1[rb + n1 * 64 + t];
    __syncthreads();
    fft512<+1>(v, ex + ly * 576, tw, t);
    const float sc = 0.1f / (512.0f * 512.0f);  // DZ * ifft2 norm
    const size_t sb = (size_t)slice * (Bn * Hn * Wn) + rb;
#pragma unroll
    for (int j = 0; j < 8; j++) {
        float2 sl = g_sampT[sb + t + 64 * j];
        v[j] = cmul(v[j], make_float2(sl.x * sc, sl.y * sc));
    }
    __syncthreads();                    // exchange buffer reuse
    fft512<-1>(v, ex + ly * 576, tw, t);
#pragma unroll
    for (int j = 0; j < 8; j++) g_b1[rb + t + 64 * j] = v[j];
}

// final inverse row + abs + crop
__global__ void k_row_final(float* __restrict__ out) {
    __shared__ float2 tw[512];
    __shared__ float2 ex[4 * 576];
    const int t = threadIdx.x, ly = threadIdx.y;
    const int line = blockIdx.x * 4 + ly;   // 0..B*OUTW-1
    const int b = line / OUTW;
    const int ho = line - b * OUTW;
    const size_t rb = ((size_t)b * Hn + (ho + PADc)) * Wn;
    for (int i = ly * 64 + t; i < 512; i += 256) tw[i] = g_tw[i];
    float2 v[8];
#pragma unroll
    for (int n1 = 0; n1 < 8; n1++) v[n1] = g_b1[rb + n1 * 64 + t];
    __syncthreads();
    fft512<+1>(v, ex + ly * 576, tw, t);
    const float sc = 1.0f / (512.0f * 512.0f);
#pragma unroll
    for (int j = 0; j < 8; j++) {
        int i = t + 64 * j;
        if (i >= PADc && i < Wn - PADc) {
            out[((size_t)b * OUTW + ho) * OUTW + (i - PADc)] =
                sqrtf(v[j].x * v[j].x + v[j].y * v[j].y) * sc;
        }
    }
}

// ---------------- fused column kernel ----------------
// MODE 0: init   — inc = fftcol(b1); write inc; ifftcol(inc) -> b1
// MODE 1: combine— inc = inc*prop + green*fftcol(b1); write inc; ifftcol(inc) -> b1
// MODE 2: final  — inc' = inc*prop + green*fftcol(b1); ifftcol(inc'*g_final) -> b1 (no inc store)
template <int MODE>
__global__ void k_col_fused() {
    __shared__ float2 tw[512];
    __shared__ float2 ex[8 * 577];
    const int c = threadIdx.x;     // 0..7
    const int ty = threadIdx.y;    // 0..63
    const int tid = ty * 8 + c;
    const int col = blockIdx.x * 8 + c;
    const size_t base = (size_t)blockIdx.y * Hn * Wn;
    if (tid < 512) tw[tid] = g_tw[tid];
    float2 v[8];
#pragma unroll
    for (int n1 = 0; n1 < 8; n1++) v[n1] = g_b1[base + (size_t)(n1 * 64 + ty) * Wn + col];
    __syncthreads();
    fft512<-1>(v, ex + c * 577, tw, ty);
#pragma unroll
    for (int j = 0; j < 8; j++) {
        int r = ty + 64 * j;
        size_t gi = base + (size_t)r * Wn + col;
        int hw = r * Wn + col;
        if (MODE == 0) {
            g_inc[gi] = v[j];
        } else {
            float2 u = cmul(g_inc[gi], g_prop[hw]);
            float2 s2 = cmul(g_green[hw], v[j]);
            float2 ni = make_float2(u.x + s2.x, u.y + s2.y);
            if (MODE == 1) {
                g_inc[gi] = ni;
                v[j] = ni;
            } else {
                v[j] = cmul(ni, g_final[hw]);
            }
        }
    }
    __syncthreads();                // exchange buffer reuse
    fft512<+1>(v, ex + c * 577, tw, ty);
#pragma unroll
    for (int j = 0; j < 8; j++) g_b1[base + (size_t)(ty + 64 * j) * Wn + col] = v[j];
}

// ---------------- launch ----------------
extern "C" void kernel_launch(void* const* d_in, const int* in_sizes, int n_in,
                              void* d_out, int out_size) {
    (void)in_sizes; (void)n_in; (void)out_size;
    const float* sre  = (const float*)d_in[0];
    const float* sim  = (const float*)d_in[1];
    const float* pre  = (const float*)d_in[2];
    const float* pim  = (const float*)d_in[3];
    const float* kz   = (const float*)d_in[4];
    const float* oabs = (const float*)d_in[5];
    const float* gm   = (const float*)d_in[6];
    const float* oph  = (const float*)d_in[7];
    float* out = (float*)d_out;

    k_precompute<<<512, 512>>>(kz, oabs, gm, oph);
    k_transpose<<<dim3(Wn / 128, Bn * Hn), 256>>>(sre, sim);

    dim3 rowB(64, 4);
    dim3 colG(Wn / 8, Bn), colB(8, 64);

    // inc0 = fft2(planewave), then ifft-col(inc0) staged into b1
    k_row_init<<<Bn * Hn / 4, rowB>>>(pre, pim);
    k_col_fused<0><<<colG, colB>>>();

    for (int s = 0; s < Sn; s++) {
        k_row_fused<<<Bn * Hn / 4, rowB>>>(s);
        if (s < Sn - 1)
            k_col_fused<1><<<colG, colB>>>();
        else
            k_col_fused<2><<<colG, colB>>>();
    }

    k_row_final<<<Bn * OUTW / 4, rowB>>>(out);
}